// round 1
// baseline (speedup 1.0000x reference)
#include <cuda_runtime.h>
#include <cstdint>

// ---------------------------------------------------------------------------
// ST-LSTM persistent kernel, fp32 (f32x2 packed FMA), single launch.
//
// Flattened recurrence: step k = t*25 + j, k in [0,1600).
//   a_cat = [ h[k-1] (512) ; h[k-25] (512) ; x[k] (256) ]   (K = 1280)
//   z     = a_cat @ [Whs; Wht; Wx] + bias                    (N = 2560)
//   i,fs,ft,g,o = split(z); c = sig(i)*tanh(g)+sig(fs)*cs+sig(ft)*ct
//   h = sig(o)*tanh(c)
//
// Grid: 128 CTAs = 16 N-tiles (160 cols) x 8 K-parts (160 rows), all resident.
// Weights persist in SMEM. Partials go to gmem; grid barrier; gates; barrier.
// ---------------------------------------------------------------------------

#define NCTA   128
#define NTHR   160

constexpr int Tt   = 64;
constexpr int Jj   = 25;
constexpr int Bb   = 64;
constexpr int Ii   = 256;
constexpr int Hh   = 512;
constexpr int G5H  = 2560;          // 5*H
constexpr int STEPS = Tt * Jj;      // 1600
constexpr int KCAT  = Hh + Hh + Ii; // 1280
constexpr int KPART = KCAT / 8;     // 160 rows per CTA
constexpr int NTILE = G5H / 16;     // 160 cols per CTA
constexpr int BH    = Bb * Hh;      // 32768
constexpr int AS    = 68;           // A_s row stride (floats), 16B-aligned rows
constexpr int WS    = 164;          // W_s row stride (floats), 16B-aligned rows
constexpr int SMEM_BYTES = (KPART * AS + KPART * WS) * 4; // 148480 B

// --------------------------- device scratch --------------------------------
__device__ float    g_xT[(size_t)STEPS * Ii * Bb];  // x transposed: [tj][i][b]
__device__ float    g_hT[32 * Hh * Bb];             // h ring, [slot][n][b]
__device__ float    g_c [32 * BH];                  // c ring, [slot][b*H + n]
__device__ float    g_part[8 * Bb * G5H];           // [kp][b][2560]
__device__ unsigned g_cnt = 0;
__device__ unsigned g_gen = 0;

// --------------------------- helpers ---------------------------------------
__device__ __forceinline__ void grid_barrier() {
    __syncthreads();
    if (threadIdx.x == 0) {
        unsigned gen = *(volatile unsigned*)&g_gen;
        __threadfence();
        unsigned rank = atomicAdd(&g_cnt, 1u);
        if (rank == NCTA - 1) {
            g_cnt = 0;
            __threadfence();
            *(volatile unsigned*)&g_gen = gen + 1u;
        } else {
            while (*(volatile unsigned*)&g_gen == gen) { __nanosleep(64); }
        }
        __threadfence();
    }
    __syncthreads();
}

__device__ __forceinline__ float fexp(float x) {
    float r;
    asm("ex2.approx.f32 %0, %1;" : "=f"(r) : "f"(x * 1.4426950408889634f));
    return r;
}
__device__ __forceinline__ float frcp(float x) {
    float r;
    asm("rcp.approx.f32 %0, %1;" : "=f"(r) : "f"(x));
    return r;
}
__device__ __forceinline__ float fsig(float x) {
    return frcp(1.0f + fexp(-x));
}
__device__ __forceinline__ float ftanh(float x) {
    // tanh(x) = 1 - 2/(1 + e^{2x}); saturates gracefully at +-1.
    return 1.0f - 2.0f * frcp(1.0f + fexp(2.0f * x));
}

// --------------------------- kernel ----------------------------------------
__global__ void __launch_bounds__(NTHR, 1)
stlstm_kernel(const float* __restrict__ x,
              const float* __restrict__ Wx,
              const float* __restrict__ Whs,
              const float* __restrict__ Wht,
              const float* __restrict__ bias,
              float* __restrict__ out)
{
    extern __shared__ float smem[];
    float* A_s = smem;                 // [KPART][AS]
    float* W_s = smem + KPART * AS;    // [KPART][WS]

    const int tid = threadIdx.x;
    const int cta = blockIdx.x;
    const int nt  = cta & 15;          // N-tile index  (16)
    const int kp  = cta >> 4;          // K-part index  (8)

    // ---------------- phase A: transpose x -> g_xT[tj][i][b] ----------------
    {
        float* tmp = smem;             // 64 x 257 floats = 65792 B (fits)
        for (int tj = cta; tj < STEPS; tj += NCTA) {
            const float* xsrc = x + (size_t)tj * (Bb * Ii);
            for (int idx = tid; idx < Bb * Ii; idx += NTHR) {
                int bb = idx >> 8, ii = idx & 255;          // idx = bb*256 + ii
                tmp[bb * 257 + ii] = xsrc[idx];
            }
            __syncthreads();
            float* xdst = g_xT + (size_t)tj * (Ii * Bb);
            for (int idx = tid; idx < Bb * Ii; idx += NTHR) {
                int ii = idx >> 6, bb = idx & 63;           // idx = ii*64 + bb
                xdst[idx] = tmp[bb * 257 + ii];
            }
            __syncthreads();
        }
    }
    grid_barrier();

    // ---------------- phase B: load persistent weight slice -----------------
    {
        const int ncol = nt * NTILE + tid;                  // 160 threads = 160 cols
        for (int r = 0; r < KPART; ++r) {
            int krow = kp * KPART + r;
            float w;
            if (krow < Hh)            w = Whs[(size_t)krow * G5H + ncol];
            else if (krow < 2 * Hh)   w = Wht[(size_t)(krow - Hh) * G5H + ncol];
            else                      w = Wx [(size_t)(krow - 2 * Hh) * G5H + ncol];
            W_s[r * WS + tid] = w;
        }
    }
    __syncthreads();

    // GEMM thread mapping: 8 b-groups x 20 n-groups
    const int bg   = tid & 7;
    const int ng   = tid >> 3;
    const int b_lo = bg * 4;           // b = b_lo..b_lo+3  and  32+b_lo..32+b_lo+3
    const int n0   = ng * 8;           // 8 cols, paired into 4 f32x2 accumulators

    // ---------------- main sequential loop ----------------------------------
    for (int step = 0; step < STEPS; ++step) {

        // ---- stage A_s[r][b] for this CTA's 160 K-rows ----
        {
            const float* hT1  = g_hT + ((step - 1)  & 31) * (Hh * Bb);
            const float* hT25 = g_hT + ((step - 25) & 31) * (Hh * Bb);
            const float* xTs  = g_xT + (size_t)step * (Ii * Bb);
            #pragma unroll 4
            for (int idx = tid; idx < KPART * Bb; idx += NTHR) {
                int r = idx >> 6, bb = idx & 63;
                int krow = kp * KPART + r;
                float v = 0.0f;
                if (krow < Hh) {
                    if (step >= 1)  v = __ldcg(hT1  + krow * Bb + bb);
                } else if (krow < 2 * Hh) {
                    if (step >= 25) v = __ldcg(hT25 + (krow - Hh) * Bb + bb);
                } else {
                    v = xTs[(krow - 2 * Hh) * Bb + bb];
                }
                A_s[r * AS + bb] = v;
            }
        }
        __syncthreads();

        // ---- GEMM: acc[8 b][4 n-pairs] over 160 K-rows (f32x2 FMA) ----
        {
            unsigned long long acc[8][4];
            #pragma unroll
            for (int i = 0; i < 8; ++i)
                #pragma unroll
                for (int p = 0; p < 4; ++p) acc[i][p] = 0ull;

            #pragma unroll 2
            for (int r = 0; r < KPART; ++r) {
                const float* arow = A_s + r * AS;
                const float* wrow = W_s + r * WS + n0;
                float4 a0 = *(const float4*)(arow + b_lo);
                float4 a1 = *(const float4*)(arow + 32 + b_lo);
                ulonglong2 wa = *(const ulonglong2*)(wrow);
                ulonglong2 wb = *(const ulonglong2*)(wrow + 4);
                const unsigned long long w0 = wa.x, w1 = wa.y, w2 = wb.x, w3 = wb.y;
                float av[8] = {a0.x, a0.y, a0.z, a0.w, a1.x, a1.y, a1.z, a1.w};
                #pragma unroll
                for (int i = 0; i < 8; ++i) {
                    unsigned long long aa;
                    asm("mov.b64 %0, {%1, %1};" : "=l"(aa) : "f"(av[i]));
                    asm("fma.rn.f32x2 %0, %1, %2, %0;" : "+l"(acc[i][0]) : "l"(aa), "l"(w0));
                    asm("fma.rn.f32x2 %0, %1, %2, %0;" : "+l"(acc[i][1]) : "l"(aa), "l"(w1));
                    asm("fma.rn.f32x2 %0, %1, %2, %0;" : "+l"(acc[i][2]) : "l"(aa), "l"(w2));
                    asm("fma.rn.f32x2 %0, %1, %2, %0;" : "+l"(acc[i][3]) : "l"(aa), "l"(w3));
                }
            }

            // ---- write partials: g_part[kp][b][nt*160 + n0 .. +8) ----
            #pragma unroll
            for (int i = 0; i < 8; ++i) {
                int brow = (i < 4) ? (b_lo + i) : (32 + b_lo + i - 4);
                float* dst = g_part + ((size_t)(kp * Bb + brow)) * G5H + nt * NTILE + n0;
                #pragma unroll
                for (int p = 0; p < 4; ++p) {
                    *(float2*)(dst + 2 * p) = *(float2*)&acc[i][p];
                }
            }
        }

        grid_barrier();   // partials visible

        // ---- gates: this CTA owns 256 of the 32768 (b,n) h-elements ----
        {
            const float* c1  = g_c + ((step - 1)  & 31) * BH;
            const float* c25 = g_c + ((step - 25) & 31) * BH;
            float*       cw  = g_c + (step & 31) * BH;
            float*       hTw = g_hT + (step & 31) * (Hh * Bb);
            float*       ow  = out + (size_t)step * BH;

            #pragma unroll
            for (int pass = 0; pass < 2; ++pass) {
                int l = tid + pass * NTHR;
                if (l < 256) {
                    int e  = cta * 256 + l;
                    int bg2 = e >> 9;          // batch index
                    int n   = e & 511;         // h column
                    float z[5];
                    #pragma unroll
                    for (int g = 0; g < 5; ++g) {
                        int col = g * Hh + n;
                        float s = bias[col];
                        #pragma unroll
                        for (int q = 0; q < 8; ++q)
                            s += __ldcg(g_part + ((size_t)(q * Bb + bg2)) * G5H + col);
                        z[g] = s;
                    }
                    float cs = (step >= 1)  ? c1 [e] : 0.0f;
                    float ct = (step >= 25) ? c25[e] : 0.0f;
                    float cc = fsig(z[0]) * ftanh(z[3]) + fsig(z[1]) * cs + fsig(z[2]) * ct;
                    float hv = fsig(z[4]) * ftanh(cc);
                    cw[e]            = cc;
                    ow[e]            = hv;
                    hTw[n * Bb + bg2] = hv;
                }
            }
        }

        grid_barrier();   // h/c visible for next step
    }
}

// --------------------------- launch ----------------------------------------
extern "C" void kernel_launch(void* const* d_in, const int* in_sizes, int n_in,
                              void* d_out, int out_size)
{
    const float* x    = (const float*)d_in[0];
    const float* Wx   = (const float*)d_in[1];
    const float* Whs  = (const float*)d_in[2];
    const float* Wht  = (const float*)d_in[3];
    const float* bias = (const float*)d_in[4];
    float*       out  = (float*)d_out;

    cudaFuncSetAttribute(stlstm_kernel,
                         cudaFuncAttributeMaxDynamicSharedMemorySize, SMEM_BYTES);
    stlstm_kernel<<<NCTA, NTHR, SMEM_BYTES>>>(x, Wx, Whs, Wht, bias, out);
}

// round 2
// speedup vs baseline: 2.8175x; 2.8175x over previous
#include <cuda_runtime.h>
#include <cstdint>

// ---------------------------------------------------------------------------
// ST-LSTM persistent kernel, fp32 f32x2, ONE grid barrier per step.
//
// 128 CTAs x 256 threads. CTA nt owns h-columns [nt*4, nt*4+4) => 20 z-cols
// (5 gates x 4), full K=1280. Weights persist in SMEM (102KB). K is split 16
// ways across threads; partials reduced through SMEM; gates computed locally.
// c-state lives entirely in CTA-private SMEM ring. Only h crosses CTAs.
// ---------------------------------------------------------------------------

#define NCTA 128
#define NTHR 256

constexpr int Bb = 64, Ii = 256, Hh = 512;
constexpr int G5H   = 2560;
constexpr int STEPS = 1600;
constexpr int HB    = Hh * Bb;     // 32768 floats per h slot
constexpr int XB    = Ii * Bb;     // 16384 floats per x step
constexpr int BH    = Bb * Hh;     // out elems per step
constexpr int NPC   = 20;          // z-cols per CTA
constexpr int KSL   = 16;          // k-slices
constexpr int KL    = 80;          // k per slice
constexpr int RS    = 1296;        // reduce-buffer row stride (floats, padded)

// SMEM float offsets
constexpr int W_OFF = 0;                    // 1280*20 = 25600
constexpr int R_OFF = 25600;                // 16*1296 = 20736
constexpr int C_OFF = R_OFF + KSL * RS;     // c ring: 25*256 = 6400
constexpr int SM_FLOATS  = C_OFF + 25 * 256;
constexpr int SMEM_BYTES = SM_FLOATS * 4;   // 210,944 B

// --------------------------- device scratch --------------------------------
__device__ float    g_xT[(size_t)STEPS * XB];  // x transposed: [tj][i][b]
__device__ float    g_hT[32 * HB];             // h ring: [slot][n][b]
__device__ unsigned g_cnt = 0;
__device__ unsigned g_gen = 0;

// --------------------------- helpers ---------------------------------------
__device__ __forceinline__ void grid_barrier() {
    __syncthreads();
    if (threadIdx.x == 0) {
        unsigned gen = *(volatile unsigned*)&g_gen;
        __threadfence();
        unsigned rank = atomicAdd(&g_cnt, 1u);
        if (rank == NCTA - 1) {
            g_cnt = 0;
            __threadfence();
            *(volatile unsigned*)&g_gen = gen + 1u;
        } else {
            while (*(volatile unsigned*)&g_gen == gen) { }
        }
        __threadfence();
    }
    __syncthreads();
}

__device__ __forceinline__ float fexp(float x) {
    float r;
    asm("ex2.approx.f32 %0, %1;" : "=f"(r) : "f"(x * 1.4426950408889634f));
    return r;
}
__device__ __forceinline__ float frcp(float x) {
    float r;
    asm("rcp.approx.f32 %0, %1;" : "=f"(r) : "f"(x));
    return r;
}
__device__ __forceinline__ float fsig(float x)  { return frcp(1.0f + fexp(-x)); }
__device__ __forceinline__ float ftanh(float x) { return 1.0f - 2.0f * frcp(1.0f + fexp(2.0f * x)); }

// --------------------------- kernel ----------------------------------------
__global__ void __launch_bounds__(NTHR, 1)
stlstm_kernel(const float* __restrict__ x,
              const float* __restrict__ Wx,
              const float* __restrict__ Whs,
              const float* __restrict__ Wht,
              const float* __restrict__ bias,
              float* __restrict__ out)
{
    extern __shared__ float sm[];
    float* W_s = sm + W_OFF;    // [1280][20]
    float* red = sm + R_OFF;    // [16][RS]
    float* c_s = sm + C_OFF;    // [25][256]

    const int t  = threadIdx.x;
    const int nt = blockIdx.x;                 // h-col tile: cols nt*4..+4

    // ---------------- phase A: transpose x -> g_xT[tj][i][b] ----------------
    {
        float* tmp = red;                      // 20736 floats >= 64*257
        for (int tj = nt; tj < STEPS; tj += NCTA) {
            const float* xsrc = x + (size_t)tj * (Bb * Ii);
            for (int idx = t; idx < Bb * Ii; idx += NTHR) {
                int bb = idx >> 8, ii = idx & 255;
                tmp[bb * 257 + ii] = xsrc[idx];
            }
            __syncthreads();
            float* xdst = g_xT + (size_t)tj * XB;
            for (int idx = t; idx < Bb * Ii; idx += NTHR) {
                int ii = idx >> 6, bb = idx & 63;
                xdst[idx] = tmp[bb * 257 + ii];
            }
            __syncthreads();
        }
    }

    // ---------------- zero the h-ring slots read before first write ---------
    {   // slots 7..31 (read as h[s-1]/h[s-25] for s<25); replay-safe reset
        float* z = g_hT + 7 * HB;
        for (int idx = nt * NTHR + t; idx < 25 * HB; idx += NCTA * NTHR) z[idx] = 0.0f;
    }

    // ---------------- zero CTA-local c ring ---------------------------------
    for (int idx = t; idx < 25 * 256; idx += NTHR) c_s[idx] = 0.0f;

    // ---------------- load persistent weight slice --------------------------
    for (int idx = t; idx < 1280 * NPC; idx += NTHR) {
        int k = idx / NPC, c = idx % NPC;
        int g = c >> 2, hc = c & 3;
        int col = g * Hh + nt * 4 + hc;
        float w;
        if (k < Hh)            w = Whs[(size_t)k * G5H + col];
        else if (k < 2 * Hh)   w = Wht[(size_t)(k - Hh) * G5H + col];
        else                   w = Wx [(size_t)(k - 2 * Hh) * G5H + col];
        W_s[idx] = w;
    }

    // per-thread bias for gate phase: thread t -> (b = t>>2, hc = t&3)
    float ba[5];
    {
        int hc = t & 3;
        #pragma unroll
        for (int g = 0; g < 5; ++g) ba[g] = bias[g * Hh + nt * 4 + hc];
    }

    grid_barrier();

    // GEMM mapping: 16 threads per k-slice, warp = 2 slices
    const int ng  = t & 1;                 // n-half: h-col pair {2ng, 2ng+1}
    const int mg  = (t >> 1) & 7;          // b-group: rows mg*8..+8
    const int ks  = t >> 4;                // k-slice 0..15
    const int b_lo = mg * 8;
    const int ng2  = ng * 2;
    const int k0   = ks * KL;

    const int bg = t >> 2;                 // gate-phase batch index
    const int hcg = t & 3;                 // gate-phase h-col

    // ---------------- main sequential loop ----------------------------------
    for (int step = 0; step < STEPS; ++step) {

        const float* h1   = g_hT + ((step - 1)  & 31) * HB;
        const float* h25m = g_hT + ((step - 25) & 31) * HB - 512 * 64;
        const float* xsm  = g_xT + (size_t)step * XB - 1024 * 64;

        unsigned long long acc[8][5];
        #pragma unroll
        for (int i = 0; i < 8; ++i)
            #pragma unroll
            for (int g = 0; g < 5; ++g) acc[i][g] = 0ull;

        float4 bufA[4][2], bufB[4][2];

#define LOADBLK(BUF, BLK)                                                     \
        {                                                                     \
            _Pragma("unroll")                                                 \
            for (int u = 0; u < 4; ++u) {                                     \
                int k = k0 + (BLK) * 4 + u;                                   \
                const float* p = xsm;                                         \
                p = (k < 1024) ? h25m : p;                                    \
                p = (k < 512)  ? h1   : p;                                    \
                p += k * 64 + b_lo;                                           \
                BUF[u][0] = __ldcg((const float4*)p);                         \
                BUF[u][1] = __ldcg((const float4*)(p + 4));                   \
            }                                                                 \
        }

#define FMABLK(BUF, BLK)                                                      \
        {                                                                     \
            _Pragma("unroll")                                                 \
            for (int u = 0; u < 4; ++u) {                                     \
                int k = k0 + (BLK) * 4 + u;                                   \
                const float* wr = W_s + k * NPC + ng2;                        \
                unsigned long long w0 = *(const unsigned long long*)(wr);     \
                unsigned long long w1 = *(const unsigned long long*)(wr + 4); \
                unsigned long long w2 = *(const unsigned long long*)(wr + 8); \
                unsigned long long w3 = *(const unsigned long long*)(wr + 12);\
                unsigned long long w4 = *(const unsigned long long*)(wr + 16);\
                float av[8] = {BUF[u][0].x, BUF[u][0].y, BUF[u][0].z,         \
                               BUF[u][0].w, BUF[u][1].x, BUF[u][1].y,         \
                               BUF[u][1].z, BUF[u][1].w};                     \
                _Pragma("unroll")                                             \
                for (int i = 0; i < 8; ++i) {                                 \
                    unsigned long long aa;                                    \
                    asm("mov.b64 %0, {%1, %1};" : "=l"(aa) : "f"(av[i]));     \
                    asm("fma.rn.f32x2 %0, %1, %2, %0;" : "+l"(acc[i][0]) : "l"(aa), "l"(w0)); \
                    asm("fma.rn.f32x2 %0, %1, %2, %0;" : "+l"(acc[i][1]) : "l"(aa), "l"(w1)); \
                    asm("fma.rn.f32x2 %0, %1, %2, %0;" : "+l"(acc[i][2]) : "l"(aa), "l"(w2)); \
                    asm("fma.rn.f32x2 %0, %1, %2, %0;" : "+l"(acc[i][3]) : "l"(aa), "l"(w3)); \
                    asm("fma.rn.f32x2 %0, %1, %2, %0;" : "+l"(acc[i][4]) : "l"(aa), "l"(w4)); \
                }                                                             \
            }                                                                 \
        }

        LOADBLK(bufA, 0)
        #pragma unroll 1
        for (int blk = 0; blk < 20; blk += 2) {
            LOADBLK(bufB, blk + 1)
            FMABLK(bufA, blk)
            if (blk + 2 < 20) LOADBLK(bufA, blk + 2)
            FMABLK(bufB, blk + 1)
        }
#undef LOADBLK
#undef FMABLK

        __syncthreads();   // red buffer free (previous gate phase done)

        // ---- store partials to SMEM reduce buffer ----
        {
            float* rrow = red + ks * RS + ng2;
            #pragma unroll
            for (int i = 0; i < 8; ++i) {
                int rb = (b_lo + i) * NPC;
                #pragma unroll
                for (int g = 0; g < 5; ++g)
                    *(float2*)(rrow + rb + g * 4) = *(float2*)&acc[i][g];
            }
        }
        __syncthreads();

        // ---- reduce 16 k-slices + gates, all local ----
        {
            float z[5];
            #pragma unroll
            for (int g = 0; g < 5; ++g) {
                float s = ba[g];
                const float* rp = red + bg * NPC + g * 4 + hcg;
                #pragma unroll
                for (int q = 0; q < KSL; ++q) s += rp[q * RS];
                z[g] = s;
            }
            float cs = c_s[((step + 24) % 25) * 256 + t];   // c[s-1]
            float ct = c_s[(step % 25) * 256 + t];          // c[s-25]
            float cc = fsig(z[0]) * ftanh(z[3]) + fsig(z[1]) * cs + fsig(z[2]) * ct;
            float hv = fsig(z[4]) * ftanh(cc);
            c_s[(step % 25) * 256 + t] = cc;

            int n = nt * 4 + hcg;
            out[(size_t)step * BH + bg * Hh + n] = hv;
            g_hT[(step & 31) * HB + n * 64 + bg] = hv;
        }

        grid_barrier();   // h visible for next step
    }
}

// --------------------------- launch ----------------------------------------
extern "C" void kernel_launch(void* const* d_in, const int* in_sizes, int n_in,
                              void* d_out, int out_size)
{
    const float* x    = (const float*)d_in[0];
    const float* Wx   = (const float*)d_in[1];
    const float* Whs  = (const float*)d_in[2];
    const float* Wht  = (const float*)d_in[3];
    const float* bias = (const float*)d_in[4];
    float*       out  = (float*)d_out;

    cudaFuncSetAttribute(stlstm_kernel,
                         cudaFuncAttributeMaxDynamicSharedMemorySize, SMEM_BYTES);
    stlstm_kernel<<<NCTA, NTHR, SMEM_BYTES>>>(x, Wx, Whs, Wht, bias, out);
}

// round 4
// speedup vs baseline: 3.5156x; 1.2478x over previous
#include <cuda_runtime.h>
#include <cstdint>

// ---------------------------------------------------------------------------
// ST-LSTM persistent kernel, fp32 f32x2. Round 4 (= Round 3 + spin backoff;
// R3 bench was an infra failure, not a kernel verdict):
//  - flag-array grid barrier (no hot-loop atomics, one L2 RT)
//  - barrier latency hidden behind next step's x-part GEMM (k rows 1024..1279)
//  - K-slice = 64 h-rows + 16 x-rows per thread (uniform x tail, constant base ptr)
// 128 CTAs x 256 thr. CTA owns 4 h-cols (20 z-cols), full K. Weights in SMEM.
// ---------------------------------------------------------------------------

#define NCTA 128
#define NTHR 256

constexpr int Bb = 64, Ii = 256, Hh = 512;
constexpr int G5H   = 2560;
constexpr int STEPS = 1600;
constexpr int HB    = Hh * Bb;     // 32768
constexpr int XB    = Ii * Bb;     // 16384
constexpr int BH    = Bb * Hh;
constexpr int NPC   = 20;          // z-cols per CTA
constexpr int KSL   = 16;          // k-slices
constexpr int RS    = 1296;        // reduce row stride (floats)

constexpr int W_OFF = 0;                    // 1280*20
constexpr int R_OFF = 25600;                // 16*1296
constexpr int C_OFF = R_OFF + KSL * RS;     // 25*256
constexpr int SM_FLOATS  = C_OFF + 25 * 256;
constexpr int SMEM_BYTES = SM_FLOATS * 4;   // 210,944 B

// --------------------------- device scratch --------------------------------
__device__ float    g_xT[(size_t)STEPS * XB];  // x transposed [tj][i][b]
__device__ float    g_hT[32 * HB];             // h ring [slot][n][b]
__device__ unsigned g_flags[NCTA * 8];         // padded arrival flags
__device__ unsigned g_cnt = 0;                 // init barrier (one-shot, self-reset)
__device__ unsigned g_gen = 0;

// --------------------------- helpers ---------------------------------------
__device__ __forceinline__ void init_barrier() {   // counter/gen style, used once
    __syncthreads();
    if (threadIdx.x == 0) {
        unsigned gen = *(volatile unsigned*)&g_gen;
        __threadfence();
        unsigned rank = atomicAdd(&g_cnt, 1u);
        if (rank == NCTA - 1) {
            g_cnt = 0;
            __threadfence();
            *(volatile unsigned*)&g_gen = gen + 1u;
        } else {
            while (*(volatile unsigned*)&g_gen == gen) { __nanosleep(64); }
        }
        __threadfence();
    }
    __syncthreads();
}

__device__ __forceinline__ void bar_arrive(int cta, int t, unsigned k) {
    __syncthreads();
    __threadfence();
    if (t == 0) *(volatile unsigned*)&g_flags[cta * 8] = k;
}
__device__ __forceinline__ void bar_wait(int t, unsigned k) {
    if (t < NCTA) {
        const unsigned* p = &g_flags[t * 8];
        unsigned v;
        asm volatile("ld.global.cg.u32 %0, [%1];" : "=r"(v) : "l"(p));
        while ((int)(v - k) < 0) {
            __nanosleep(32);
            asm volatile("ld.global.cg.u32 %0, [%1];" : "=r"(v) : "l"(p));
        }
    }
    __syncthreads();
    __threadfence();
}

__device__ __forceinline__ float fexp(float x) {
    float r;
    asm("ex2.approx.f32 %0, %1;" : "=f"(r) : "f"(x * 1.4426950408889634f));
    return r;
}
__device__ __forceinline__ float frcp(float x) {
    float r;
    asm("rcp.approx.f32 %0, %1;" : "=f"(r) : "f"(x));
    return r;
}
__device__ __forceinline__ float fsig(float x)  { return frcp(1.0f + fexp(-x)); }
__device__ __forceinline__ float ftanh(float x) { return 1.0f - 2.0f * frcp(1.0f + fexp(2.0f * x)); }

// --------------------------- kernel ----------------------------------------
__global__ void __launch_bounds__(NTHR, 1)
stlstm_kernel(const float* __restrict__ x,
              const float* __restrict__ Wx,
              const float* __restrict__ Whs,
              const float* __restrict__ Wht,
              const float* __restrict__ bias,
              float* __restrict__ out)
{
    extern __shared__ float sm[];
    float* W_s = sm + W_OFF;
    float* red = sm + R_OFF;
    float* c_s = sm + C_OFF;

    const int t   = threadIdx.x;
    const int cta = blockIdx.x;
    const int nt  = cta;

    // -------- pre-barrier init: x transpose, ring zero, flags, weights ------
    if (t == 0) *(volatile unsigned*)&g_flags[cta * 8] = 0u;
    {
        float* tmp = red;
        for (int tj = cta; tj < STEPS; tj += NCTA) {
            const float* xsrc = x + (size_t)tj * (Bb * Ii);
            for (int idx = t; idx < Bb * Ii; idx += NTHR) {
                int bb = idx >> 8, ii = idx & 255;
                tmp[bb * 257 + ii] = xsrc[idx];
            }
            __syncthreads();
            float* xdst = g_xT + (size_t)tj * XB;
            for (int idx = t; idx < Bb * Ii; idx += NTHR) {
                int ii = idx >> 6, bb = idx & 63;
                xdst[idx] = tmp[bb * 257 + ii];
            }
            __syncthreads();
        }
    }
    {   // zero h-ring slots 7..31 (all early reads land there)
        float* z = g_hT + 7 * HB;
        for (int idx = cta * NTHR + t; idx < 25 * HB; idx += NCTA * NTHR) z[idx] = 0.0f;
    }
    for (int idx = t; idx < 25 * 256; idx += NTHR) c_s[idx] = 0.0f;

    for (int idx = t; idx < 1280 * NPC; idx += NTHR) {
        int k = idx / NPC, c = idx % NPC;
        int g = c >> 2, hc = c & 3;
        int col = g * Hh + nt * 4 + hc;
        float w;
        if (k < Hh)            w = Whs[(size_t)k * G5H + col];
        else if (k < 2 * Hh)   w = Wht[(size_t)(k - Hh) * G5H + col];
        else                   w = Wx [(size_t)(k - 2 * Hh) * G5H + col];
        W_s[idx] = w;
    }

    float ba[5];
    {
        int hc = t & 3;
        #pragma unroll
        for (int g = 0; g < 5; ++g) ba[g] = bias[g * Hh + nt * 4 + hc];
    }

    init_barrier();   // x ready, rings zeroed, flags zeroed

    // GEMM mapping: thread = (ng, mg, ks); slice = 64 h-rows + 16 x-rows
    const int ng   = t & 1;
    const int mg   = (t >> 1) & 7;
    const int ks   = t >> 4;
    const int b_lo = mg * 8;
    const int ng2  = ng * 2;
    const int khW  = ks * 64;            // W row base, h part
    const int kxW  = 1024 + ks * 16;     // W row base, x part

    const int bg  = t >> 2;
    const int hcg = t & 3;

    unsigned long long acc[8][5];
    float4 bufA[4][2], bufB[4][2];

#define ZERO_ACC()                                                            \
    {  _Pragma("unroll")                                                      \
       for (int i = 0; i < 8; ++i)                                            \
           _Pragma("unroll")                                                  \
           for (int g = 0; g < 5; ++g) acc[i][g] = 0ull; }

#define LOADBLK(BUF, PA, BLK)                                                 \
    {  _Pragma("unroll")                                                      \
       for (int u = 0; u < 4; ++u) {                                          \
           const float* p = (PA) + ((BLK) * 4 + u) * 64;                      \
           BUF[u][0] = __ldcg((const float4*)p);                              \
           BUF[u][1] = __ldcg((const float4*)(p + 4));                        \
       } }

#define FMABLK(BUF, KWB, BLK)                                                 \
    {  _Pragma("unroll")                                                      \
       for (int u = 0; u < 4; ++u) {                                          \
           const float* wr = W_s + ((KWB) + (BLK) * 4 + u) * NPC + ng2;       \
           unsigned long long w0 = *(const unsigned long long*)(wr);          \
           unsigned long long w1 = *(const unsigned long long*)(wr + 4);      \
           unsigned long long w2 = *(const unsigned long long*)(wr + 8);      \
           unsigned long long w3 = *(const unsigned long long*)(wr + 12);     \
           unsigned long long w4 = *(const unsigned long long*)(wr + 16);     \
           float av[8] = {BUF[u][0].x, BUF[u][0].y, BUF[u][0].z, BUF[u][0].w, \
                          BUF[u][1].x, BUF[u][1].y, BUF[u][1].z, BUF[u][1].w};\
           _Pragma("unroll")                                                  \
           for (int i = 0; i < 8; ++i) {                                      \
               unsigned long long aa;                                         \
               asm("mov.b64 %0, {%1, %1};" : "=l"(aa) : "f"(av[i]));          \
               asm("fma.rn.f32x2 %0, %1, %2, %0;" : "+l"(acc[i][0]) : "l"(aa), "l"(w0)); \
               asm("fma.rn.f32x2 %0, %1, %2, %0;" : "+l"(acc[i][1]) : "l"(aa), "l"(w1)); \
               asm("fma.rn.f32x2 %0, %1, %2, %0;" : "+l"(acc[i][2]) : "l"(aa), "l"(w2)); \
               asm("fma.rn.f32x2 %0, %1, %2, %0;" : "+l"(acc[i][3]) : "l"(aa), "l"(w3)); \
               asm("fma.rn.f32x2 %0, %1, %2, %0;" : "+l"(acc[i][4]) : "l"(aa), "l"(w4)); \
           } } }

#define XGEMM(S)                                                              \
    {  const float* pX = g_xT + (size_t)(S) * XB + (ks * 16) * 64 + b_lo;     \
       LOADBLK(bufA, pX, 0)                                                   \
       LOADBLK(bufB, pX, 1)                                                   \
       FMABLK(bufA, kxW, 0)                                                   \
       LOADBLK(bufA, pX, 2)                                                   \
       FMABLK(bufB, kxW, 1)                                                   \
       LOADBLK(bufB, pX, 3)                                                   \
       FMABLK(bufA, kxW, 2)                                                   \
       FMABLK(bufB, kxW, 3) }

    // prologue: x-part of step 0
    ZERO_ACC()
    XGEMM(0)

    // ---------------- main sequential loop ----------------------------------
    for (int step = 0; step < STEPS; ++step) {

        // ---- h-part GEMM: 16 blocks over this thread's 64 h-rows ----
        {
            const float* h1  = g_hT + ((step - 1)  & 31) * HB;
            const float* h25 = g_hT + ((step - 25) & 31) * HB;
            const float* pH  = ((ks < 8) ? (h1 + khW * 64)
                                         : (h25 + (khW - 512) * 64)) + b_lo;
            LOADBLK(bufA, pH, 0)
            #pragma unroll 1
            for (int blk = 0; blk < 16; blk += 2) {
                LOADBLK(bufB, pH, blk + 1)
                FMABLK(bufA, khW, blk)
                if (blk + 2 < 16) LOADBLK(bufA, pH, blk + 2)
                FMABLK(bufB, khW, blk + 1)
            }
        }

        __syncthreads();   // red buffer free (previous gate phase done)

        // ---- store partials ----
        {
            float* rrow = red + ks * RS + ng2;
            #pragma unroll
            for (int i = 0; i < 8; ++i) {
                int rb = (b_lo + i) * NPC;
                #pragma unroll
                for (int g = 0; g < 5; ++g)
                    *(float2*)(rrow + rb + g * 4) = *(float2*)&acc[i][g];
            }
        }
        __syncthreads();

        // ---- reduce + gates (local) ----
        {
            float z[5];
            #pragma unroll
            for (int g = 0; g < 5; ++g) {
                float s = ba[g];
                const float* rp = red + bg * NPC + g * 4 + hcg;
                #pragma unroll
                for (int q = 0; q < KSL; ++q) s += rp[q * RS];
                z[g] = s;
            }
            float cs = c_s[((step + 24) % 25) * 256 + t];
            float ct = c_s[(step % 25) * 256 + t];
            float cc = fsig(z[0]) * ftanh(z[3]) + fsig(z[1]) * cs + fsig(z[2]) * ct;
            float hv = fsig(z[4]) * ftanh(cc);
            c_s[(step % 25) * 256 + t] = cc;

            int n = nt * 4 + hcg;
            out[(size_t)step * BH + bg * Hh + n] = hv;
            g_hT[(step & 31) * HB + n * 64 + bg] = hv;
        }

        // ---- arrive, then hide barrier behind next step's x-part ----
        bar_arrive(cta, t, (unsigned)(step + 1));
        if (step + 1 < STEPS) {
            ZERO_ACC()
            XGEMM(step + 1)
            bar_wait(t, (unsigned)(step + 1));
        }
    }
#undef ZERO_ACC
#undef LOADBLK
#undef FMABLK
#undef XGEMM
}

// --------------------------- launch ----------------------------------------
extern "C" void kernel_launch(void* const* d_in, const int* in_sizes, int n_in,
                              void* d_out, int out_size)
{
    const float* x    = (const float*)d_in[0];
    const float* Wx   = (const float*)d_in[1];
    const float* Whs  = (const float*)d_in[2];
    const float* Wht  = (const float*)d_in[3];
    const float* bias = (const float*)d_in[4];
    float*       out  = (float*)d_out;

    cudaFuncSetAttribute(stlstm_kernel,
                         cudaFuncAttributeMaxDynamicSharedMemorySize, SMEM_BYTES);
    stlstm_kernel<<<NCTA, NTHR, SMEM_BYTES>>>(x, Wx, Whs, Wht, bias, out);
}

// round 5
// speedup vs baseline: 4.2859x; 1.2191x over previous
#include <cuda_runtime.h>
#include <cstdint>

// ---------------------------------------------------------------------------
// ST-LSTM persistent kernel, fp32 f32x2. Round 5:
//  - 512 threads/CTA (16 warps, 4/SMSP) for latency hiding; m-tile 8->4
//  - ks warp-uniform => each LDG.128 covers one full 256B row (fewer wavefronts)
//  - flag-array grid barrier + barrier hidden behind next step's x-part GEMM
// 128 CTAs. CTA owns 4 h-cols (20 z-cols), full K=1280. Weights in SMEM.
// ---------------------------------------------------------------------------

#define NCTA 128
#define NTHR 512

constexpr int Bb = 64, Ii = 256, Hh = 512;
constexpr int G5H   = 2560;
constexpr int STEPS = 1600;
constexpr int HB    = Hh * Bb;     // 32768
constexpr int XB    = Ii * Bb;     // 16384
constexpr int BH    = Bb * Hh;
constexpr int NPC   = 20;          // z-cols per CTA
constexpr int KSL   = 16;          // k-slices
constexpr int RS    = 1296;        // reduce row stride (floats, 16-mod-32 stagger)

constexpr int W_OFF = 0;                    // 1280*20
constexpr int R_OFF = 25600;                // 16*1296
constexpr int C_OFF = R_OFF + KSL * RS;     // 25*256
constexpr int SM_FLOATS  = C_OFF + 25 * 256;
constexpr int SMEM_BYTES = SM_FLOATS * 4;   // 210,944 B

// --------------------------- device scratch --------------------------------
__device__ float    g_xT[(size_t)STEPS * XB];  // x transposed [tj][i][b]
__device__ float    g_hT[32 * HB];             // h ring [slot][n][b]
__device__ unsigned g_flags[NCTA * 8];         // padded arrival flags
__device__ unsigned g_cnt = 0;                 // init barrier (one-shot, self-reset)
__device__ unsigned g_gen = 0;

// --------------------------- helpers ---------------------------------------
__device__ __forceinline__ void init_barrier() {   // counter/gen style, used once
    __syncthreads();
    if (threadIdx.x == 0) {
        unsigned gen = *(volatile unsigned*)&g_gen;
        __threadfence();
        unsigned rank = atomicAdd(&g_cnt, 1u);
        if (rank == NCTA - 1) {
            g_cnt = 0;
            __threadfence();
            *(volatile unsigned*)&g_gen = gen + 1u;
        } else {
            while (*(volatile unsigned*)&g_gen == gen) { __nanosleep(64); }
        }
        __threadfence();
    }
    __syncthreads();
}

__device__ __forceinline__ void bar_arrive(int cta, int t, unsigned k) {
    __syncthreads();
    __threadfence();
    if (t == 0) *(volatile unsigned*)&g_flags[cta * 8] = k;
}
__device__ __forceinline__ void bar_wait(int t, unsigned k) {
    if (t < NCTA) {
        const unsigned* p = &g_flags[t * 8];
        unsigned v;
        asm volatile("ld.global.cg.u32 %0, [%1];" : "=r"(v) : "l"(p));
        while ((int)(v - k) < 0) {
            __nanosleep(32);
            asm volatile("ld.global.cg.u32 %0, [%1];" : "=r"(v) : "l"(p));
        }
    }
    __syncthreads();
    __threadfence();
}

__device__ __forceinline__ float fexp(float x) {
    float r;
    asm("ex2.approx.f32 %0, %1;" : "=f"(r) : "f"(x * 1.4426950408889634f));
    return r;
}
__device__ __forceinline__ float frcp(float x) {
    float r;
    asm("rcp.approx.f32 %0, %1;" : "=f"(r) : "f"(x));
    return r;
}
__device__ __forceinline__ float fsig(float x)  { return frcp(1.0f + fexp(-x)); }
__device__ __forceinline__ float ftanh(float x) { return 1.0f - 2.0f * frcp(1.0f + fexp(2.0f * x)); }

// --------------------------- kernel ----------------------------------------
__global__ void __launch_bounds__(NTHR, 1)
stlstm_kernel(const float* __restrict__ x,
              const float* __restrict__ Wx,
              const float* __restrict__ Whs,
              const float* __restrict__ Wht,
              const float* __restrict__ bias,
              float* __restrict__ out)
{
    extern __shared__ float sm[];
    float* W_s = sm + W_OFF;
    float* red = sm + R_OFF;
    float* c_s = sm + C_OFF;

    const int t   = threadIdx.x;
    const int cta = blockIdx.x;
    const int nt  = cta;

    // -------- pre-barrier init: flags, x transpose, ring zero, weights ------
    if (t == 0) *(volatile unsigned*)&g_flags[cta * 8] = 0u;
    {
        float* tmp = red;                      // 20736 floats >= 64*257
        for (int tj = cta; tj < STEPS; tj += NCTA) {
            const float* xsrc = x + (size_t)tj * (Bb * Ii);
            for (int idx = t; idx < Bb * Ii; idx += NTHR) {
                int bb = idx >> 8, ii = idx & 255;
                tmp[bb * 257 + ii] = xsrc[idx];
            }
            __syncthreads();
            float* xdst = g_xT + (size_t)tj * XB;
            for (int idx = t; idx < Bb * Ii; idx += NTHR) {
                int ii = idx >> 6, bb = idx & 63;
                xdst[idx] = tmp[bb * 257 + ii];
            }
            __syncthreads();
        }
    }
    {   // zero h-ring slots 7..31 (all early reads land there)
        float* z = g_hT + 7 * HB;
        for (int idx = cta * NTHR + t; idx < 25 * HB; idx += NCTA * NTHR) z[idx] = 0.0f;
    }
    for (int idx = t; idx < 25 * 256; idx += NTHR) c_s[idx] = 0.0f;

    for (int idx = t; idx < 1280 * NPC; idx += NTHR) {
        int k = idx / NPC, c = idx % NPC;
        int g = c >> 2, hc = c & 3;
        int col = g * Hh + nt * 4 + hc;
        float w;
        if (k < Hh)            w = Whs[(size_t)k * G5H + col];
        else if (k < 2 * Hh)   w = Wht[(size_t)(k - Hh) * G5H + col];
        else                   w = Wx [(size_t)(k - 2 * Hh) * G5H + col];
        W_s[idx] = w;
    }

    float ba[5];
    {
        int hc = t & 3;
        #pragma unroll
        for (int g = 0; g < 5; ++g) ba[g] = bias[g * Hh + nt * 4 + hc];
    }

    init_barrier();   // x ready, rings zeroed, flags zeroed

    // GEMM mapping: thread = (ng, mg, ks); ks warp-uniform.
    // Thread tile: 4 b-rows x 10 n-cols x 80 k-rows (64 h + 16 x).
    const int ng   = t & 1;
    const int mg   = (t >> 1) & 15;
    const int ks   = t >> 5;
    const int b_lo = mg * 4;
    const int ng2  = ng * 2;
    const int khW  = ks * 64;            // W row base, h part
    const int kxW  = 1024 + ks * 16;     // W row base, x part

    const int bg  = t >> 2;              // gate phase (t < 256)
    const int hcg = t & 3;

    unsigned long long acc[4][5];
    float4 bufA[4], bufB[4];

#define ZERO_ACC()                                                            \
    {  _Pragma("unroll")                                                      \
       for (int i = 0; i < 4; ++i)                                            \
           _Pragma("unroll")                                                  \
           for (int g = 0; g < 5; ++g) acc[i][g] = 0ull; }

#define LOADBLK(BUF, PA, BLK)                                                 \
    {  _Pragma("unroll")                                                      \
       for (int u = 0; u < 4; ++u)                                            \
           BUF[u] = __ldcg((const float4*)((PA) + ((BLK) * 4 + u) * 64));     \
    }

#define FMABLK(BUF, KWB, BLK)                                                 \
    {  _Pragma("unroll")                                                      \
       for (int u = 0; u < 4; ++u) {                                          \
           const float* wr = W_s + ((KWB) + (BLK) * 4 + u) * NPC + ng2;       \
           unsigned long long w0 = *(const unsigned long long*)(wr);          \
           unsigned long long w1 = *(const unsigned long long*)(wr + 4);      \
           unsigned long long w2 = *(const unsigned long long*)(wr + 8);      \
           unsigned long long w3 = *(const unsigned long long*)(wr + 12);     \
           unsigned long long w4 = *(const unsigned long long*)(wr + 16);     \
           float av[4] = {BUF[u].x, BUF[u].y, BUF[u].z, BUF[u].w};            \
           _Pragma("unroll")                                                  \
           for (int i = 0; i < 4; ++i) {                                      \
               unsigned long long aa;                                         \
               asm("mov.b64 %0, {%1, %1};" : "=l"(aa) : "f"(av[i]));          \
               asm("fma.rn.f32x2 %0, %1, %2, %0;" : "+l"(acc[i][0]) : "l"(aa), "l"(w0)); \
               asm("fma.rn.f32x2 %0, %1, %2, %0;" : "+l"(acc[i][1]) : "l"(aa), "l"(w1)); \
               asm("fma.rn.f32x2 %0, %1, %2, %0;" : "+l"(acc[i][2]) : "l"(aa), "l"(w2)); \
               asm("fma.rn.f32x2 %0, %1, %2, %0;" : "+l"(acc[i][3]) : "l"(aa), "l"(w3)); \
               asm("fma.rn.f32x2 %0, %1, %2, %0;" : "+l"(acc[i][4]) : "l"(aa), "l"(w4)); \
           } } }

#define XGEMM(S)                                                              \
    {  const float* pX = g_xT + (size_t)(S) * XB + (ks * 16) * 64 + b_lo;     \
       LOADBLK(bufA, pX, 0)                                                   \
       LOADBLK(bufB, pX, 1)                                                   \
       FMABLK(bufA, kxW, 0)                                                   \
       LOADBLK(bufA, pX, 2)                                                   \
       FMABLK(bufB, kxW, 1)                                                   \
       LOADBLK(bufB, pX, 3)                                                   \
       FMABLK(bufA, kxW, 2)                                                   \
       FMABLK(bufB, kxW, 3) }

    // prologue: x-part of step 0
    ZERO_ACC()
    XGEMM(0)

    // ---------------- main sequential loop ----------------------------------
    for (int step = 0; step < STEPS; ++step) {

        // ---- h-part GEMM: 16 blocks over this thread's 64 h-rows ----
        {
            const float* h1  = g_hT + ((step - 1)  & 31) * HB;
            const float* h25 = g_hT + ((step - 25) & 31) * HB;
            const float* pH  = ((ks < 8) ? (h1 + khW * 64)
                                         : (h25 + (khW - 512) * 64)) + b_lo;
            LOADBLK(bufA, pH, 0)
            #pragma unroll 1
            for (int blk = 0; blk < 16; blk += 2) {
                LOADBLK(bufB, pH, blk + 1)
                FMABLK(bufA, khW, blk)
                if (blk + 2 < 16) LOADBLK(bufA, pH, blk + 2)
                FMABLK(bufB, khW, blk + 1)
            }
        }

        __syncthreads();   // red buffer free (previous gate phase done)

        // ---- store partials ----
        {
            float* rrow = red + ks * RS + ng2;
            #pragma unroll
            for (int i = 0; i < 4; ++i) {
                int rb = (b_lo + i) * NPC;
                #pragma unroll
                for (int g = 0; g < 5; ++g)
                    *(float2*)(rrow + rb + g * 4) = *(float2*)&acc[i][g];
            }
        }
        __syncthreads();

        // ---- reduce + gates (local, threads 0..255) ----
        if (t < 256) {
            float z[5];
            #pragma unroll
            for (int g = 0; g < 5; ++g) {
                float s = ba[g];
                const float* rp = red + bg * NPC + g * 4 + hcg;
                #pragma unroll
                for (int q = 0; q < KSL; ++q) s += rp[q * RS];
                z[g] = s;
            }
            float cs = c_s[((step + 24) % 25) * 256 + t];
            float ct = c_s[(step % 25) * 256 + t];
            float cc = fsig(z[0]) * ftanh(z[3]) + fsig(z[1]) * cs + fsig(z[2]) * ct;
            float hv = fsig(z[4]) * ftanh(cc);
            c_s[(step % 25) * 256 + t] = cc;

            int n = nt * 4 + hcg;
            out[(size_t)step * BH + bg * Hh + n] = hv;
            g_hT[(step & 31) * HB + n * 64 + bg] = hv;
        }

        // ---- arrive, then hide barrier behind next step's x-part ----
        bar_arrive(cta, t, (unsigned)(step + 1));
        if (step + 1 < STEPS) {
            ZERO_ACC()
            XGEMM(step + 1)
            bar_wait(t, (unsigned)(step + 1));
        }
    }
#undef ZERO_ACC
#undef LOADBLK
#undef FMABLK
#undef XGEMM
}

// --------------------------- launch ----------------------------------------
extern "C" void kernel_launch(void* const* d_in, const int* in_sizes, int n_in,
                              void* d_out, int out_size)
{
    const float* x    = (const float*)d_in[0];
    const float* Wx   = (const float*)d_in[1];
    const float* Whs  = (const float*)d_in[2];
    const float* Wht  = (const float*)d_in[3];
    const float* bias = (const float*)d_in[4];
    float*       out  = (float*)d_out;

    cudaFuncSetAttribute(stlstm_kernel,
                         cudaFuncAttributeMaxDynamicSharedMemorySize, SMEM_BYTES);
    stlstm_kernel<<<NCTA, NTHR, SMEM_BYTES>>>(x, Wx, Whs, Wht, bias, out);
}